// round 16
// baseline (speedup 1.0000x reference)
#include <cuda_runtime.h>
#include <cuda_bf16.h>
#include <cstdint>
#include <cstddef>

// Problem constants
#define B_SZ   4096
#define N_TOK  32
#define H_HEADS 8
#define D_HEAD 64
#define HID    512
#define M_ROWS (B_SZ * N_TOK)   // 131072
#define QKV_COLS (3 * HID)      // 1536

// ---------------------------------------------------------------------------
// Scratch (__device__ globals; allocation-free rule), 16B aligned.
// ---------------------------------------------------------------------------
__device__ __align__(16) float g_qkv[(size_t)M_ROWS * QKV_COLS];
__device__ __align__(16) __nv_bfloat16 g_xhi[(size_t)M_ROWS * HID];
__device__ __align__(16) __nv_bfloat16 g_xlo[(size_t)M_ROWS * HID];
__device__ __align__(16) __nv_bfloat16 g_chi[(size_t)M_ROWS * HID];
__device__ __align__(16) __nv_bfloat16 g_clo[(size_t)M_ROWS * HID];
__device__ __align__(16) __nv_bfloat16 g_w1hi[(size_t)QKV_COLS * HID];
__device__ __align__(16) __nv_bfloat16 g_w1lo[(size_t)QKV_COLS * HID];
__device__ __align__(16) __nv_bfloat16 g_w2hi[(size_t)HID * HID];
__device__ __align__(16) __nv_bfloat16 g_w2lo[(size_t)HID * HID];

__device__ __forceinline__ uint32_t smem_u32(const void* p) {
    uint32_t a;
    asm("{ .reg .u64 t; cvta.to.shared.u64 t, %1; cvt.u32.u64 %0, t; }"
        : "=r"(a) : "l"(p));
    return a;
}
__device__ __forceinline__ void cp_async16(uint32_t dst, const void* src) {
    asm volatile("cp.async.cg.shared.global [%0], [%1], 16;"
        :: "r"(dst), "l"(src) : "memory");
}

// ---------------------------------------------------------------------------
// f32 -> (bf16 hi, bf16 lo) split, 4 elems/thread
// ---------------------------------------------------------------------------
__global__ __launch_bounds__(256) void split_f32(
    const float* __restrict__ in, __nv_bfloat16* __restrict__ hi,
    __nv_bfloat16* __restrict__ lo, size_t n4)
{
    size_t i = (size_t)blockIdx.x * blockDim.x + threadIdx.x;
    if (i >= n4) return;
    float4 x = reinterpret_cast<const float4*>(in)[i];
    __nv_bfloat16 h[4], l[4];
    float xs[4] = {x.x, x.y, x.z, x.w};
#pragma unroll
    for (int j = 0; j < 4; j++) {
        h[j] = __float2bfloat16_rn(xs[j]);
        l[j] = __float2bfloat16_rn(xs[j] - __bfloat162float(h[j]));
    }
    reinterpret_cast<ushort4*>(hi)[i] = make_ushort4(
        __bfloat16_as_ushort(h[0]), __bfloat16_as_ushort(h[1]),
        __bfloat16_as_ushort(h[2]), __bfloat16_as_ushort(h[3]));
    reinterpret_cast<ushort4*>(lo)[i] = make_ushort4(
        __bfloat16_as_ushort(l[0]), __bfloat16_as_ushort(l[1]),
        __bfloat16_as_ushort(l[2]), __bfloat16_as_ushort(l[3]));
}

// ---------------------------------------------------------------------------
// GEMM via mma.sync m16n8k16 bf16, 3-pass hi/lo split:
//   C = Ahi@Bhi^T + Alo@Bhi^T + Ahi@Blo^T + bias   (fp32 accum/out)
// Block tile 128x128, 256 threads (8 warps 2x4), warp tile 64x32.
// BK=64 chunks, 2-stage cp.async buffer, 2-deep fragment pipeline,
// hoisted incremental ldmatrix addressing. Row pad 72 bf16 (conflict-free).
// ---------------------------------------------------------------------------
#define GK      512
#define BKC     64
#define NCH     24            // 3 passes * 8 chunks of 64
#define PADB    72            // smem row stride in bf16 (144 B)
#define ROWB    (PADB * 2)    // 144
#define TILEB   (128 * ROWB)  // 18432 B per operand per stage
#define STGB    (2 * TILEB)   // 36864 B per stage (A + B)
#define SMEM_DYN (2 * STGB + 512)  // 74240 B

__global__ __launch_bounds__(256, 2) void gemm_mma_x3(
    const __nv_bfloat16* __restrict__ Ahi, const __nv_bfloat16* __restrict__ Alo,
    const __nv_bfloat16* __restrict__ Bhi, const __nv_bfloat16* __restrict__ Blo,
    const float* __restrict__ bias, float* __restrict__ C, int Nfull)
{
    extern __shared__ char dsm[];
    const int tid  = threadIdx.x;
    const int wid  = tid >> 5;
    const int lane = tid & 31;
    const int m_blk = blockIdx.y * 128;
    const int n_blk = blockIdx.x * 128;

    const uint32_t s0 = smem_u32(dsm);
    float* sbias = reinterpret_cast<float*>(dsm + 2 * STGB);
    if (tid < 128) sbias[tid] = bias[n_blk + tid];

    const __nv_bfloat16* Aseg[3] = {Ahi, Alo, Ahi};
    const __nv_bfloat16* Bseg[3] = {Bhi, Bhi, Blo};

    // cp.async mapping: thread -> row tid/2, 64B half tid&1; 4x16B per operand
    const int lr = tid >> 1;
    const int lh = tid & 1;
    const uint32_t so = (uint32_t)lr * ROWB + lh * 64;

    auto load_chunk = [&](int stg, int c) {
        int pass = c >> 3;
        int k0 = (c & 7) * BKC;
        const __nv_bfloat16* Ap = Aseg[pass] + (size_t)(m_blk + lr) * GK + k0 + lh * 32;
        const __nv_bfloat16* Bp = Bseg[pass] + (size_t)(n_blk + lr) * GK + k0 + lh * 32;
        uint32_t as = s0 + stg * STGB + so;
        uint32_t bs = as + TILEB;
#pragma unroll
        for (int i = 0; i < 4; i++) {
            cp_async16(as + i * 16, Ap + i * 8);
            cp_async16(bs + i * 16, Bp + i * 8);
        }
        asm volatile("cp.async.commit_group;" ::: "memory");
    };

    float acc[4][4][4];
#pragma unroll
    for (int i = 0; i < 4; i++)
#pragma unroll
        for (int j = 0; j < 4; j++)
#pragma unroll
            for (int e = 0; e < 4; e++) acc[i][j][e] = 0.f;

    const int wm = (wid & 1) * 64;
    const int wn = (wid >> 1) * 32;
    const int lrow = lane & 15;
    const int lcol = (lane >> 4) * 8;

    // Hoisted ldmatrix byte offsets within a stage (add stage base + ks*2)
    uint32_t aoff[4], boff[2];
#pragma unroll
    for (int mt = 0; mt < 4; mt++)
        aoff[mt] = (uint32_t)(wm + mt * 16 + lrow) * ROWB + lcol * 2;
#pragma unroll
    for (int nt2 = 0; nt2 < 2; nt2++)
        boff[nt2] = TILEB + (uint32_t)(wn + nt2 * 16 + lrow) * ROWB + lcol * 2;

    uint32_t af[2][4][4], bf[2][2][4];

    load_chunk(0, 0);

    for (int c = 0; c < NCH; c++) {
        const int b = c & 1;
        if (c + 1 < NCH) {
            load_chunk(b ^ 1, c + 1);
            asm volatile("cp.async.wait_group 1;" ::: "memory");
        } else {
            asm volatile("cp.async.wait_group 0;" ::: "memory");
        }
        __syncthreads();

        const uint32_t sb = s0 + b * STGB;

        // preload fragments for ks=0
#pragma unroll
        for (int mt = 0; mt < 4; mt++)
            asm volatile(
                "ldmatrix.sync.aligned.m8n8.x4.shared.b16 {%0,%1,%2,%3}, [%4];"
                : "=r"(af[0][mt][0]), "=r"(af[0][mt][1]),
                  "=r"(af[0][mt][2]), "=r"(af[0][mt][3])
                : "r"(sb + aoff[mt]));
#pragma unroll
        for (int nt2 = 0; nt2 < 2; nt2++)
            asm volatile(
                "ldmatrix.sync.aligned.m8n8.x4.shared.b16 {%0,%1,%2,%3}, [%4];"
                : "=r"(bf[0][nt2][0]), "=r"(bf[0][nt2][1]),
                  "=r"(bf[0][nt2][2]), "=r"(bf[0][nt2][3])
                : "r"(sb + boff[nt2]));

#pragma unroll
        for (int ks16 = 0; ks16 < 4; ks16++) {
            const int cur = ks16 & 1;
            const int nxt = cur ^ 1;
            if (ks16 < 3) {
                const uint32_t kb = (uint32_t)(ks16 + 1) * 32;  // 16 elems * 2B
#pragma unroll
                for (int mt = 0; mt < 4; mt++)
                    asm volatile(
                        "ldmatrix.sync.aligned.m8n8.x4.shared.b16 {%0,%1,%2,%3}, [%4];"
                        : "=r"(af[nxt][mt][0]), "=r"(af[nxt][mt][1]),
                          "=r"(af[nxt][mt][2]), "=r"(af[nxt][mt][3])
                        : "r"(sb + aoff[mt] + kb));
#pragma unroll
                for (int nt2 = 0; nt2 < 2; nt2++)
                    asm volatile(
                        "ldmatrix.sync.aligned.m8n8.x4.shared.b16 {%0,%1,%2,%3}, [%4];"
                        : "=r"(bf[nxt][nt2][0]), "=r"(bf[nxt][nt2][1]),
                          "=r"(bf[nxt][nt2][2]), "=r"(bf[nxt][nt2][3])
                        : "r"(sb + boff[nt2] + kb));
            }
#pragma unroll
            for (int mt = 0; mt < 4; mt++)
#pragma unroll
                for (int nt = 0; nt < 4; nt++) {
                    uint32_t bb0 = bf[cur][nt >> 1][nt & 1];
                    uint32_t bb1 = bf[cur][nt >> 1][(nt & 1) + 2];
                    asm volatile(
                        "mma.sync.aligned.m16n8k16.row.col.f32.bf16.bf16.f32 "
                        "{%0,%1,%2,%3}, {%4,%5,%6,%7}, {%8,%9}, {%0,%1,%2,%3};"
                        : "+f"(acc[mt][nt][0]), "+f"(acc[mt][nt][1]),
                          "+f"(acc[mt][nt][2]), "+f"(acc[mt][nt][3])
                        : "r"(af[cur][mt][0]), "r"(af[cur][mt][1]),
                          "r"(af[cur][mt][2]), "r"(af[cur][mt][3]),
                          "r"(bb0), "r"(bb1));
                }
        }
        __syncthreads();
    }

    // Epilogue
    const int erow = lane >> 2;
    const int ecol = (lane & 3) * 2;
#pragma unroll
    for (int mt = 0; mt < 4; mt++) {
#pragma unroll
        for (int nt = 0; nt < 4; nt++) {
            int colL = wn + nt * 8 + ecol;
            float bv0 = sbias[colL], bv1 = sbias[colL + 1];
            size_t r0 = (size_t)(m_blk + wm + mt * 16 + erow);
            float2 v0 = make_float2(acc[mt][nt][0] + bv0, acc[mt][nt][1] + bv1);
            float2 v1 = make_float2(acc[mt][nt][2] + bv0, acc[mt][nt][3] + bv1);
            *reinterpret_cast<float2*>(&C[r0 * Nfull + n_blk + colL]) = v0;
            *reinterpret_cast<float2*>(&C[(r0 + 8) * Nfull + n_blk + colL]) = v1;
        }
    }
}

// ---------------------------------------------------------------------------
// Attention: one block per (b, h). fp32 qkv in; attn probs (f32) + ctx as
// bf16 hi/lo out. Mask dtype detection proven in R8.
// ---------------------------------------------------------------------------
__global__ __launch_bounds__(128) void attn_kernel(
    const float* __restrict__ qkv, const void* __restrict__ mask_raw,
    float* __restrict__ attn_out,
    __nv_bfloat16* __restrict__ chi, __nv_bfloat16* __restrict__ clo)
{
    const int bh = blockIdx.x;
    const int b = bh >> 3, h = bh & 7;

    __shared__ float q[32][64], k[32][64], v[32][64];
    __shared__ float s[32][33];
    __shared__ unsigned char msk[1024];
    __shared__ int mode;

    const int tid = threadIdx.x;

    if (tid == 0) {
        const unsigned char* m8 = (const unsigned char*)mask_raw;
        const int* m32 = (const int*)mask_raw;
        bool u8ok = true;
#pragma unroll
        for (int i = 0; i < 32; i++) u8ok &= (m8[i * 33] == 1);
        if (u8ok) { mode = 0; }
        else {
            bool i32ok = true;
#pragma unroll
            for (int i = 0; i < 8; i++) i32ok &= (m32[i * 33] == 1);
            mode = i32ok ? 1 : 2;
        }
    }

    const float* base = qkv + (size_t)b * (N_TOK * QKV_COLS) + h * D_HEAD;
    for (int i = tid; i < 512; i += 128) {
        int n = i >> 4, d4 = (i & 15) * 4;
        const float* rp = base + (size_t)n * QKV_COLS + d4;
        *reinterpret_cast<float4*>(&q[n][d4]) = *reinterpret_cast<const float4*>(rp);
        *reinterpret_cast<float4*>(&k[n][d4]) = *reinterpret_cast<const float4*>(rp + HID);
        *reinterpret_cast<float4*>(&v[n][d4]) = *reinterpret_cast<const float4*>(rp + 2 * HID);
    }
    __syncthreads();

    {
        int md = mode;
        const unsigned char* m8 = (const unsigned char*)mask_raw;
        const int* m32 = (const int*)mask_raw;
        const float* mf = (const float*)mask_raw;
        for (int i = tid; i < 1024; i += 128) {
            unsigned char mv;
            if (md == 0)      mv = (m8[i] != 0);
            else if (md == 1) mv = (m32[i] != 0);
            else              mv = (mf[i] != 0.0f);
            msk[i] = mv;
        }
    }
    __syncthreads();

    for (int e = tid; e < 1024; e += 128) {
        int i = e >> 5, j = e & 31;
        float accv = 0.f;
#pragma unroll
        for (int d = 0; d < 64; d++) accv = fmaf(q[i][d], k[j][d], accv);
        s[i][j] = msk[e] ? accv * 0.125f : -1e9f;
    }
    __syncthreads();

    if (tid < 32) {
        int i = tid;
        float mx = -3.0e38f;
#pragma unroll
        for (int j = 0; j < 32; j++) mx = fmaxf(mx, s[i][j]);
        float p[32];
        float sum = 0.f;
#pragma unroll
        for (int j = 0; j < 32; j++) { p[j] = expf(s[i][j] - mx); sum += p[j]; }
        float inv = 1.0f / sum;
#pragma unroll
        for (int j = 0; j < 32; j++) s[i][j] = p[j] * inv;
    }
    __syncthreads();

    float* aout = attn_out + (size_t)bh * 1024;
    for (int e = tid; e < 1024; e += 128) aout[e] = s[e >> 5][e & 31];

    size_t coff = (size_t)b * (N_TOK * HID) + h * D_HEAD;
    for (int e = tid; e < 2048; e += 128) {
        int n = e >> 6, d = e & 63;
        float accv = 0.f;
#pragma unroll
        for (int m = 0; m < 32; m++) accv = fmaf(s[n][m], v[m][d], accv);
        __nv_bfloat16 hv = __float2bfloat16_rn(accv);
        __nv_bfloat16 lv = __float2bfloat16_rn(accv - __bfloat162float(hv));
        size_t idx = coff + (size_t)n * HID + d;
        chi[idx] = hv;
        clo[idx] = lv;
    }
}

// ---------------------------------------------------------------------------
// Inputs: module_states f32 [4096,32,512], sparse_mask [32,32] (detected),
// Wqkv f32 [1536,512], bqkv [1536], Wo f32 [512,512], bo [512]
// Output: output [4096,32,512] f32, then attn [4096,8,32,32] f32.
// ---------------------------------------------------------------------------
extern "C" void kernel_launch(void* const* d_in, const int* in_sizes, int n_in,
                              void* d_out, int out_size)
{
    const float* x    = (const float*)d_in[0];
    const void*  mask = d_in[1];
    const float* Wqkv = (const float*)d_in[2];
    const float* bqkv = (const float*)d_in[3];
    const float* Wo   = (const float*)d_in[4];
    const float* bo   = (const float*)d_in[5];

    float* out  = (float*)d_out;
    float* attn = out + (size_t)M_ROWS * HID;

    float *qkv_p;
    __nv_bfloat16 *xhi, *xlo, *chi, *clo, *w1hi, *w1lo, *w2hi, *w2lo;
    cudaGetSymbolAddress((void**)&qkv_p, g_qkv);
    cudaGetSymbolAddress((void**)&xhi, g_xhi);
    cudaGetSymbolAddress((void**)&xlo, g_xlo);
    cudaGetSymbolAddress((void**)&chi, g_chi);
    cudaGetSymbolAddress((void**)&clo, g_clo);
    cudaGetSymbolAddress((void**)&w1hi, g_w1hi);
    cudaGetSymbolAddress((void**)&w1lo, g_w1lo);
    cudaGetSymbolAddress((void**)&w2hi, g_w2hi);
    cudaGetSymbolAddress((void**)&w2lo, g_w2lo);

    cudaFuncSetAttribute(gemm_mma_x3,
        cudaFuncAttributeMaxDynamicSharedMemorySize, SMEM_DYN);

    // 0) split inputs into bf16 hi/lo
    {
        size_t n4 = (size_t)M_ROWS * HID / 4;
        split_f32<<<(unsigned)((n4 + 255) / 256), 256>>>(x, xhi, xlo, n4);
        size_t w1 = (size_t)QKV_COLS * HID / 4;
        split_f32<<<(unsigned)((w1 + 255) / 256), 256>>>(Wqkv, w1hi, w1lo, w1);
        size_t w2 = (size_t)HID * HID / 4;
        split_f32<<<(unsigned)((w2 + 255) / 256), 256>>>(Wo, w2hi, w2lo, w2);
    }

    // 1) QKV = X @ Wqkv^T + bqkv
    {
        dim3 grid(QKV_COLS / 128, M_ROWS / 128);   // (12, 1024)
        gemm_mma_x3<<<grid, 256, SMEM_DYN>>>(xhi, xlo, w1hi, w1lo, bqkv,
                                             qkv_p, QKV_COLS);
    }

    // 2) attention per (b, h); ctx emitted as bf16 hi/lo
    attn_kernel<<<B_SZ * H_HEADS, 128>>>(qkv_p, mask, attn, chi, clo);

    // 3) output = ctx @ Wo^T + bo
    {
        dim3 grid(HID / 128, M_ROWS / 128);        // (4, 1024)
        gemm_mma_x3<<<grid, 256, SMEM_DYN>>>(chi, clo, w2hi, w2lo, bo,
                                             out, HID);
    }
}

// round 17
// speedup vs baseline: 2.9667x; 2.9667x over previous
#include <cuda_runtime.h>
#include <cuda_bf16.h>
#include <cstdint>
#include <cstddef>

// Problem constants
#define B_SZ   4096
#define N_TOK  32
#define H_HEADS 8
#define D_HEAD 64
#define HID    512
#define M_ROWS (B_SZ * N_TOK)   // 131072
#define QKV_COLS (3 * HID)      // 1536

// ---------------------------------------------------------------------------
// Scratch (__device__ globals; allocation-free rule), 16B aligned.
// ---------------------------------------------------------------------------
__device__ __align__(16) float g_qkv[(size_t)M_ROWS * QKV_COLS];
__device__ __align__(16) float g_xt [(size_t)M_ROWS * HID];      // x, tf32-rounded
__device__ __align__(16) float g_ctx[(size_t)M_ROWS * HID];      // ctx, tf32-rounded
__device__ __align__(16) float g_w1t[(size_t)QKV_COLS * HID];    // Wqkv tf32
__device__ __align__(16) float g_w2t[(size_t)HID * HID];         // Wo tf32

__device__ __forceinline__ uint32_t smem_u32(const void* p) {
    uint32_t a;
    asm("{ .reg .u64 t; cvta.to.shared.u64 t, %1; cvt.u32.u64 %0, t; }"
        : "=r"(a) : "l"(p));
    return a;
}
__device__ __forceinline__ void cp_async16(uint32_t dst, const void* src) {
    asm volatile("cp.async.cg.shared.global [%0], [%1], 16;"
        :: "r"(dst), "l"(src) : "memory");
}
__device__ __forceinline__ float rna_tf32(float x) {
    uint32_t r;
    asm("cvt.rna.tf32.f32 %0, %1;" : "=r"(r) : "f"(x));
    return __uint_as_float(r);
}

// ---------------------------------------------------------------------------
// f32 -> tf32 (round-to-nearest) elementwise, 4 elems/thread
// ---------------------------------------------------------------------------
__global__ __launch_bounds__(256) void conv_tf32(
    const float* __restrict__ in, float* __restrict__ outp, size_t n4)
{
    size_t i = (size_t)blockIdx.x * blockDim.x + threadIdx.x;
    if (i >= n4) return;
    float4 x = reinterpret_cast<const float4*>(in)[i];
    x.x = rna_tf32(x.x); x.y = rna_tf32(x.y);
    x.z = rna_tf32(x.z); x.w = rna_tf32(x.w);
    reinterpret_cast<float4*>(outp)[i] = x;
}

// ---------------------------------------------------------------------------
// GEMM via mma.sync m16n8k8 tf32 (single pass): C = A @ B^T + bias.
// A:[M,512] tf32-rounded fp32, B:[N,512] tf32-rounded fp32.
// Block 128x128, 256 threads (8 warps 2x4), warp tile 64x32.
// BK=32 tf32 (128B/row), 16 chunks, 2-stage cp.async (R13-proven structure).
// ---------------------------------------------------------------------------
#define GK      512
#define BKC     32
#define NCH     16
#define ROWB    144             // row stride bytes (36 tf32): conflict-free
#define TILEB   (128 * ROWB)    // 18432 B
#define STGB    (2 * TILEB)     // 36864 B (A + B)
#define SMEM_DYN (2 * STGB + 512)

__global__ __launch_bounds__(256, 2) void gemm_tf32(
    const float* __restrict__ At, const float* __restrict__ Bt,
    const float* __restrict__ bias, float* __restrict__ C, int Nfull)
{
    extern __shared__ char dsm[];
    const int tid  = threadIdx.x;
    const int wid  = tid >> 5;
    const int lane = tid & 31;
    const int m_blk = blockIdx.y * 128;
    const int n_blk = blockIdx.x * 128;

    const uint32_t s0 = smem_u32(dsm);
    float* sbias = reinterpret_cast<float*>(dsm + 2 * STGB);
    if (tid < 128) sbias[tid] = bias[n_blk + tid];

    // cp.async mapping: 1024 16B-units per operand per chunk; 4 per thread
    auto load_chunk = [&](int stg, int c) {
        int k0 = c * BKC;
        const float* Ap = At + (size_t)m_blk * GK + k0;
        const float* Bp = Bt + (size_t)n_blk * GK + k0;
        uint32_t as = s0 + stg * STGB;
        uint32_t bs = as + TILEB;
#pragma unroll
        for (int p = 0; p < 4; p++) {
            int u = tid + 256 * p;
            int row = u >> 3, c16 = u & 7;
            uint32_t soff = (uint32_t)row * ROWB + c16 * 16;
            cp_async16(as + soff, Ap + (size_t)row * GK + c16 * 4);
            cp_async16(bs + soff, Bp + (size_t)row * GK + c16 * 4);
        }
        asm volatile("cp.async.commit_group;" ::: "memory");
    };

    float acc[4][4][4];
#pragma unroll
    for (int i = 0; i < 4; i++)
#pragma unroll
        for (int j = 0; j < 4; j++)
#pragma unroll
            for (int e = 0; e < 4; e++) acc[i][j][e] = 0.f;

    const int wm = (wid & 1) * 64;
    const int wn = (wid >> 1) * 32;

    // A ldmatrix lane mapping (m16k8 tf32 == four 8x4-tf32 tiles):
    const int lrow = lane & 15;
    const int lcolB = (lane >> 4) * 16;      // byte offset 0 or 16
    // B ldmatrix lane mapping (two n8k8 tiles per x4):
    const int brow = (lane & 7) + ((lane >> 4) & 1) * 8;
    const int bbyte = ((lane >> 3) & 1) * 16;

    uint32_t aoff[4], boff[2];
#pragma unroll
    for (int mt = 0; mt < 4; mt++)
        aoff[mt] = (uint32_t)(wm + mt * 16 + lrow) * ROWB + lcolB;
#pragma unroll
    for (int j = 0; j < 2; j++)
        boff[j] = TILEB + (uint32_t)(wn + j * 16 + brow) * ROWB + bbyte;

    load_chunk(0, 0);

    for (int c = 0; c < NCH; c++) {
        const int b = c & 1;
        if (c + 1 < NCH) {
            load_chunk(b ^ 1, c + 1);
            asm volatile("cp.async.wait_group 1;" ::: "memory");
        } else {
            asm volatile("cp.async.wait_group 0;" ::: "memory");
        }
        __syncthreads();

        const uint32_t sb = s0 + b * STGB;

#pragma unroll
        for (int ks = 0; ks < 4; ks++) {           // k8 steps, 32B each
            const uint32_t kb = (uint32_t)ks * 32;
            uint32_t af[4][4], bf[2][4];
#pragma unroll
            for (int mt = 0; mt < 4; mt++)
                asm volatile(
                    "ldmatrix.sync.aligned.m8n8.x4.shared.b16 {%0,%1,%2,%3}, [%4];"
                    : "=r"(af[mt][0]), "=r"(af[mt][1]),
                      "=r"(af[mt][2]), "=r"(af[mt][3])
                    : "r"(sb + aoff[mt] + kb));
#pragma unroll
            for (int j = 0; j < 2; j++)
                asm volatile(
                    "ldmatrix.sync.aligned.m8n8.x4.shared.b16 {%0,%1,%2,%3}, [%4];"
                    : "=r"(bf[j][0]), "=r"(bf[j][1]),
                      "=r"(bf[j][2]), "=r"(bf[j][3])
                    : "r"(sb + boff[j] + kb));
#pragma unroll
            for (int mt = 0; mt < 4; mt++)
#pragma unroll
                for (int nt = 0; nt < 4; nt++) {
                    uint32_t bb0 = bf[nt >> 1][(nt & 1) * 2];
                    uint32_t bb1 = bf[nt >> 1][(nt & 1) * 2 + 1];
                    asm volatile(
                        "mma.sync.aligned.m16n8k8.row.col.f32.tf32.tf32.f32 "
                        "{%0,%1,%2,%3}, {%4,%5,%6,%7}, {%8,%9}, {%0,%1,%2,%3};"
                        : "+f"(acc[mt][nt][0]), "+f"(acc[mt][nt][1]),
                          "+f"(acc[mt][nt][2]), "+f"(acc[mt][nt][3])
                        : "r"(af[mt][0]), "r"(af[mt][1]),
                          "r"(af[mt][2]), "r"(af[mt][3]),
                          "r"(bb0), "r"(bb1));
                }
        }
        __syncthreads();
    }

    // Epilogue: c0,c1 -> (m = lane/4, n = 2*(lane%4)); c2,c3 -> m+8
    const int erow = lane >> 2;
    const int ecol = (lane & 3) * 2;
#pragma unroll
    for (int mt = 0; mt < 4; mt++) {
#pragma unroll
        for (int nt = 0; nt < 4; nt++) {
            int colL = wn + nt * 8 + ecol;
            float bv0 = sbias[colL], bv1 = sbias[colL + 1];
            size_t r0 = (size_t)(m_blk + wm + mt * 16 + erow);
            float2 v0 = make_float2(acc[mt][nt][0] + bv0, acc[mt][nt][1] + bv1);
            float2 v1 = make_float2(acc[mt][nt][2] + bv0, acc[mt][nt][3] + bv1);
            *reinterpret_cast<float2*>(&C[r0 * Nfull + n_blk + colL]) = v0;
            *reinterpret_cast<float2*>(&C[(r0 + 8) * Nfull + n_blk + colL]) = v1;
        }
    }
}

// ---------------------------------------------------------------------------
// Attention: one block per (b, h). fp32 qkv in; attn probs (f32) out; ctx
// written tf32-rounded fp32 (feeds tf32 GEMM2). Mask detection proven in R8.
// ---------------------------------------------------------------------------
__global__ __launch_bounds__(128) void attn_kernel(
    const float* __restrict__ qkv, const void* __restrict__ mask_raw,
    float* __restrict__ attn_out, float* __restrict__ ctx)
{
    const int bh = blockIdx.x;
    const int b = bh >> 3, h = bh & 7;

    __shared__ float q[32][64], k[32][64], v[32][64];
    __shared__ float s[32][33];
    __shared__ unsigned char msk[1024];
    __shared__ int mode;

    const int tid = threadIdx.x;

    if (tid == 0) {
        const unsigned char* m8 = (const unsigned char*)mask_raw;
        const int* m32 = (const int*)mask_raw;
        bool u8ok = true;
#pragma unroll
        for (int i = 0; i < 32; i++) u8ok &= (m8[i * 33] == 1);
        if (u8ok) { mode = 0; }
        else {
            bool i32ok = true;
#pragma unroll
            for (int i = 0; i < 8; i++) i32ok &= (m32[i * 33] == 1);
            mode = i32ok ? 1 : 2;
        }
    }

    const float* base = qkv + (size_t)b * (N_TOK * QKV_COLS) + h * D_HEAD;
    for (int i = tid; i < 512; i += 128) {
        int n = i >> 4, d4 = (i & 15) * 4;
        const float* rp = base + (size_t)n * QKV_COLS + d4;
        *reinterpret_cast<float4*>(&q[n][d4]) = *reinterpret_cast<const float4*>(rp);
        *reinterpret_cast<float4*>(&k[n][d4]) = *reinterpret_cast<const float4*>(rp + HID);
        *reinterpret_cast<float4*>(&v[n][d4]) = *reinterpret_cast<const float4*>(rp + 2 * HID);
    }
    __syncthreads();

    {
        int md = mode;
        const unsigned char* m8 = (const unsigned char*)mask_raw;
        const int* m32 = (const int*)mask_raw;
        const float* mf = (const float*)mask_raw;
        for (int i = tid; i < 1024; i += 128) {
            unsigned char mv;
            if (md == 0)      mv = (m8[i] != 0);
            else if (md == 1) mv = (m32[i] != 0);
            else              mv = (mf[i] != 0.0f);
            msk[i] = mv;
        }
    }
    __syncthreads();

    for (int e = tid; e < 1024; e += 128) {
        int i = e >> 5, j = e & 31;
        float accv = 0.f;
#pragma unroll
        for (int d = 0; d < 64; d++) accv = fmaf(q[i][d], k[j][d], accv);
        s[i][j] = msk[e] ? accv * 0.125f : -1e9f;
    }
    __syncthreads();

    if (tid < 32) {
        int i = tid;
        float mx = -3.0e38f;
#pragma unroll
        for (int j = 0; j < 32; j++) mx = fmaxf(mx, s[i][j]);
        float p[32];
        float sum = 0.f;
#pragma unroll
        for (int j = 0; j < 32; j++) { p[j] = expf(s[i][j] - mx); sum += p[j]; }
        float inv = 1.0f / sum;
#pragma unroll
        for (int j = 0; j < 32; j++) s[i][j] = p[j] * inv;
    }
    __syncthreads();

    float* aout = attn_out + (size_t)bh * 1024;
    for (int e = tid; e < 1024; e += 128) aout[e] = s[e >> 5][e & 31];

    // ctx = attn @ v, tf32-rounded for GEMM2
    size_t coff = (size_t)b * (N_TOK * HID) + h * D_HEAD;
    for (int e = tid; e < 2048; e += 128) {
        int n = e >> 6, d = e & 63;
        float accv = 0.f;
#pragma unroll
        for (int m = 0; m < 32; m++) accv = fmaf(s[n][m], v[m][d], accv);
        ctx[coff + (size_t)n * HID + d] = rna_tf32(accv);
    }
}

// ---------------------------------------------------------------------------
// Inputs: module_states f32 [4096,32,512], sparse_mask [32,32] (detected),
// Wqkv f32 [1536,512], bqkv [1536], Wo f32 [512,512], bo [512]
// Output: output [4096,32,512] f32, then attn [4096,8,32,32] f32.
// ---------------------------------------------------------------------------
extern "C" void kernel_launch(void* const* d_in, const int* in_sizes, int n_in,
                              void* d_out, int out_size)
{
    const float* x    = (const float*)d_in[0];
    const void*  mask = d_in[1];
    const float* Wqkv = (const float*)d_in[2];
    const float* bqkv = (const float*)d_in[3];
    const float* Wo   = (const float*)d_in[4];
    const float* bo   = (const float*)d_in[5];

    float* out  = (float*)d_out;
    float* attn = out + (size_t)M_ROWS * HID;

    float *qkv_p, *xt, *ctx, *w1t, *w2t;
    cudaGetSymbolAddress((void**)&qkv_p, g_qkv);
    cudaGetSymbolAddress((void**)&xt,  g_xt);
    cudaGetSymbolAddress((void**)&ctx, g_ctx);
    cudaGetSymbolAddress((void**)&w1t, g_w1t);
    cudaGetSymbolAddress((void**)&w2t, g_w2t);

    cudaFuncSetAttribute(gemm_tf32,
        cudaFuncAttributeMaxDynamicSharedMemorySize, SMEM_DYN);

    // 0) round operands to tf32 (RN — avoids mma's biased truncation)
    {
        size_t n4 = (size_t)M_ROWS * HID / 4;
        conv_tf32<<<(unsigned)((n4 + 255) / 256), 256>>>(x, xt, n4);
        size_t w1 = (size_t)QKV_COLS * HID / 4;
        conv_tf32<<<(unsigned)((w1 + 255) / 256), 256>>>(Wqkv, w1t, w1);
        size_t w2 = (size_t)HID * HID / 4;
        conv_tf32<<<(unsigned)((w2 + 255) / 256), 256>>>(Wo, w2t, w2);
    }

    // 1) QKV = X @ Wqkv^T + bqkv
    {
        dim3 grid(QKV_COLS / 128, M_ROWS / 128);   // (12, 1024)
        gemm_tf32<<<grid, 256, SMEM_DYN>>>(xt, w1t, bqkv, qkv_p, QKV_COLS);
    }

    // 2) attention per (b, h); ctx emitted tf32-rounded
    attn_kernel<<<B_SZ * H_HEADS, 128>>>(qkv_p, mask, attn, ctx);

    // 3) output = ctx @ Wo^T + bo
    {
        dim3 grid(HID / 128, M_ROWS / 128);        // (4, 1024)
        gemm_tf32<<<grid, 256, SMEM_DYN>>>(ctx, w2t, bo, out, HID);
    }
}